// round 7
// baseline (speedup 1.0000x reference)
#include <cuda_runtime.h>
#include <cstdint>
#include <math.h>

#define N_ROWS 65536
#define DIM    512
#define KCODES 1024

#define QUANT_OFF 1
#define PERP_OFF  (1 + N_ROWS * DIM)
#define ENC_OFF   (2 + (size_t)N_ROWS * DIM)

// pass1: CTA = 128 rows x 1024 codes (8 chunks of 128). 256 thr = 16x16,
// each thread 8 rows x 8 codes, int8 dp4a over K=512 (128 int32 packs).
#define NK4   128
#define MARGIN 0.0625f
#define CAND_CAP 64

// pass1 smem byte offsets
#define SA    0                 // A8 transposed [128 k4][128 rows] int32 = 65536
#define SB    65536             // B8 2 bufs x [128 k4][128 codes] int32
#define SB_BUF 65536
#define SWN   196608            // 128 f32 wnorm
#define SWS   197120            // 128 f32 wscale
#define SXN   197632            // 128 f32 xnorm
#define SXS   198144            // 128 f32 2*xscale
#define SMIN  198656            // 128 u64
#define SCNT  199680            // 128 int
#define SCAND 200192            // 128 x 64 u16 = 16384
#define SMTOT 216576

// ---- scratch ----
__device__ __align__(16) int g_x8[(size_t)(N_ROWS / 128)][NK4][128];  // 33.5MB
__device__ __align__(16) int g_w8[KCODES / 128][NK4][128];            // 512KB
__device__ float  g_wnorm[KCODES];
__device__ float  g_ws[KCODES];      // max|w|/127
__device__ float  g_xnorm[N_ROWS];
__device__ float  g_xs[N_ROWS];      // 2*max|x|/127
__device__ int    g_idx[N_ROWS];
__device__ int    g_counts[KCODES];
__device__ unsigned short g_cand[(size_t)N_ROWS * CAND_CAP];
__device__ int    g_ccount[N_ROWS];
__device__ double g_sse;

// ---- helpers (baseline PTX only) ----
static __device__ __forceinline__ uint32_t smem_u32(const void* p) {
    uint32_t a;
    asm("{ .reg .u64 t; cvta.to.shared.u64 t, %1; cvt.u32.u64 %0, t; }" : "=r"(a) : "l"(p));
    return a;
}
static __device__ __forceinline__ uint64_t cvta_g(const void* p) {
    uint64_t a; asm("cvta.to.global.u64 %0, %1;" : "=l"(a) : "l"(p)); return a;
}
static __device__ __forceinline__ void cp16(uint32_t s, uint64_t g) {
    asm volatile("cp.async.cg.shared.global [%0], [%1], 16;" :: "r"(s), "l"(g));
}
#define CP_COMMIT() asm volatile("cp.async.commit_group;")
#define CP_WAIT0()  asm volatile("cp.async.wait_group 0;")

static __device__ __forceinline__ int dp4a(int a, int b, int c) {
    int d; asm("dp4a.s32.s32 %0, %1, %2, %3;" : "=r"(d) : "r"(a), "r"(b), "r"(c));
    return d;
}
static __device__ __forceinline__ int q8(float v, float inv) {
    return __float2int_rn(fminf(fmaxf(v * inv, -127.f), 127.f));
}
static __device__ __forceinline__ int pack4(float4 v, float inv) {
    int a = q8(v.x, inv), b = q8(v.y, inv), c = q8(v.z, inv), d = q8(v.w, inv);
    return (a & 0xFF) | ((b & 0xFF) << 8) | ((c & 0xFF) << 16) | ((d & 0xFF) << 24);
}

// ============================================================
// prep W: wnorm, wscale, int8 transpose; zero counts/sse
// 128 blocks x 8 warps; warp -> one code
// ============================================================
__global__ void vq_wprep(const float* __restrict__ W) {
    int w = threadIdx.x >> 5, lane = threadIdx.x & 31;
    int code = blockIdx.x * 8 + w;
    const float4* row = (const float4*)(W + (size_t)code * DIM);
    float4 v[4];
    float s = 0.f, m = 0.f;
#pragma unroll
    for (int j = 0; j < 4; j++) {
        v[j] = row[lane * 4 + j];
        s += v[j].x * v[j].x + v[j].y * v[j].y + v[j].z * v[j].z + v[j].w * v[j].w;
        m = fmaxf(m, fmaxf(fmaxf(fabsf(v[j].x), fabsf(v[j].y)),
                           fmaxf(fabsf(v[j].z), fabsf(v[j].w))));
    }
#pragma unroll
    for (int o = 16; o > 0; o >>= 1) {
        s += __shfl_xor_sync(0xffffffffu, s, o);
        m = fmaxf(m, __shfl_xor_sync(0xffffffffu, m, o));
    }
    m = fmaxf(m, 1e-30f);
    if (lane == 0) { g_wnorm[code] = s; g_ws[code] = m * (1.f / 127.f); }
    float inv = 127.f / m;
#pragma unroll
    for (int j = 0; j < 4; j++)
        g_w8[code >> 7][lane * 4 + j][code & 127] = pack4(v[j], inv);
    if (blockIdx.x == 0) {
        for (int i = threadIdx.x; i < KCODES; i += blockDim.x) g_counts[i] = 0;
        if (threadIdx.x == 0) g_sse = 0.0;
    }
}

// ============================================================
// prep X: xnorm, xscale, int8 + transpose via smem
// 2048 blocks x 256 thr; block = 32 rows; warp -> 4 rows
// ============================================================
__global__ void __launch_bounds__(256)
vq_xprep(const float* __restrict__ X) {
    __shared__ int srow[32][132];        // [row-in-block][k4], padded
    const int tid = threadIdx.x;
    const int w = tid >> 5, lane = tid & 31;
    const int r0 = blockIdx.x * 32;

#pragma unroll
    for (int i = 0; i < 4; i++) {
        int row = r0 + w * 4 + i;
        const float4* xp = (const float4*)(X + (size_t)row * DIM);
        float4 v[4];
        float s = 0.f, m = 0.f;
#pragma unroll
        for (int j = 0; j < 4; j++) {
            v[j] = xp[lane * 4 + j];
            s += v[j].x * v[j].x + v[j].y * v[j].y + v[j].z * v[j].z + v[j].w * v[j].w;
            m = fmaxf(m, fmaxf(fmaxf(fabsf(v[j].x), fabsf(v[j].y)),
                               fmaxf(fabsf(v[j].z), fabsf(v[j].w))));
        }
#pragma unroll
        for (int o = 16; o > 0; o >>= 1) {
            s += __shfl_xor_sync(0xffffffffu, s, o);
            m = fmaxf(m, __shfl_xor_sync(0xffffffffu, m, o));
        }
        m = fmaxf(m, 1e-30f);
        if (lane == 0) { g_xnorm[row] = s; g_xs[row] = 2.f * m * (1.f / 127.f); }
        float inv = 127.f / m;
#pragma unroll
        for (int j = 0; j < 4; j++)
            srow[w * 4 + i][lane * 4 + j] = pack4(v[j], inv);
    }
    __syncthreads();

    // transposed write: thread -> k4 = tid/2, 16 rows; int4 = 4 rows per store
    const int k4 = tid >> 1, rb = (tid & 1) * 16;
    const int tile = r0 >> 7, rin = (r0 & 127) + rb;
    int* dst = &g_x8[tile][k4][rin];
#pragma unroll
    for (int u = 0; u < 4; u++) {
        int4 val;
        val.x = srow[rb + u * 4 + 0][k4];
        val.y = srow[rb + u * 4 + 1][k4];
        val.z = srow[rb + u * 4 + 2][k4];
        val.w = srow[rb + u * 4 + 3][k4];
        *(int4*)(dst + u * 4) = val;
    }
}

// ============================================================
// pass 1: int8 dp4a GEMM + candidate collection
// ============================================================
__global__ void __launch_bounds__(256, 1)
vq_pass1(void) {
    extern __shared__ __align__(16) char smem[];
    const uint32_t sb = smem_u32(smem);
    const int tid = threadIdx.x;
    const int tr = tid >> 4, tc = tid & 15;
    const int blk = blockIdx.x;
    const int r0 = blk * 128;

    float* sWn = (float*)(smem + SWN);
    float* sWs = (float*)(smem + SWS);
    float* sXn = (float*)(smem + SXN);
    float* sXs = (float*)(smem + SXS);
    unsigned long long* sMin = (unsigned long long*)(smem + SMIN);
    int* sCnt = (int*)(smem + SCNT);
    unsigned short* sCand = (unsigned short*)(smem + SCAND);

    // stage A (64KB) + B chunk0 (64KB)
    {
        uint64_t asrc = cvta_g(g_x8) + (size_t)blk * 65536;
        uint64_t bsrc = cvta_g(g_w8);
#pragma unroll
        for (int i = 0; i < 16; i++) {
            int f = tid + i * 256;
            cp16(sb + SA + f * 16, asrc + (size_t)f * 16);
            cp16(sb + SB + f * 16, bsrc + (size_t)f * 16);
        }
    }
    CP_COMMIT();

    if (tid < 128) {
        sXn[tid] = g_xnorm[r0 + tid];
        sXs[tid] = g_xs[r0 + tid];
        sMin[tid] = 0xFFFFFFFFFFFFFFFFull;
        sCnt[tid] = 0;
    }

    for (int nc = 0; nc < 8; nc++) {
        const int c0 = nc * 128;
        CP_WAIT0();
        __syncthreads();                     // B(nc) ready; prev epilogue done
        if (tid < 128) {
            sWn[tid] = g_wnorm[c0 + tid];
            sWs[tid] = g_ws[c0 + tid];
        }
        __syncthreads();

        const int buf = nc & 1;
        if (nc < 7) {                        // prefetch next chunk into other buf
            uint64_t bsrc = cvta_g(g_w8) + (size_t)(nc + 1) * 65536;
#pragma unroll
            for (int i = 0; i < 16; i++) {
                int f = tid + i * 256;
                cp16(sb + SB + (buf ^ 1) * SB_BUF + f * 16, bsrc + (size_t)f * 16);
            }
            CP_COMMIT();
        }

        int acc[8][8];
#pragma unroll
        for (int i = 0; i < 8; i++)
#pragma unroll
            for (int j = 0; j < 8; j++) acc[i][j] = 0;

        const char* pA = smem + SA + tr * 32;
        const char* pB = smem + SB + buf * SB_BUF + tc * 32;
#pragma unroll 2
        for (int k4 = 0; k4 < NK4; k4++) {
            int4 a0 = *(const int4*)(pA + k4 * 512);
            int4 a1 = *(const int4*)(pA + k4 * 512 + 16);
            int4 b0 = *(const int4*)(pB + k4 * 512);
            int4 b1 = *(const int4*)(pB + k4 * 512 + 16);
            int av[8] = {a0.x, a0.y, a0.z, a0.w, a1.x, a1.y, a1.z, a1.w};
            int bv[8] = {b0.x, b0.y, b0.z, b0.w, b1.x, b1.y, b1.z, b1.w};
#pragma unroll
            for (int i = 0; i < 8; i++)
#pragma unroll
                for (int j = 0; j < 8; j++)
                    acc[i][j] = dp4a(av[i], bv[j], acc[i][j]);
        }

        // ---- epilogue: per-row min, then candidate collection ----
#pragma unroll
        for (int i = 0; i < 8; i++) {
            int row = tr * 8 + i;
            float xn = sXn[row], xs2 = sXs[row];
            unsigned long long pk = 0xFFFFFFFFFFFFFFFFull;
#pragma unroll
            for (int j = 0; j < 8; j++) {
                int col = tc * 8 + j;
                float d = (xn + sWn[col]) - xs2 * sWs[col] * (float)acc[i][j];
                unsigned long long p =
                    ((unsigned long long)__float_as_uint(d) << 32)
                    | (unsigned)(c0 + col);
                if (p < pk) pk = p;
            }
            atomicMin(&sMin[row], pk);
        }
        __syncthreads();
#pragma unroll
        for (int i = 0; i < 8; i++) {
            int row = tr * 8 + i;
            float xn = sXn[row], xs2 = sXs[row];
            float thr = __uint_as_float((unsigned)(sMin[row] >> 32)) + MARGIN;
#pragma unroll
            for (int j = 0; j < 8; j++) {
                int col = tc * 8 + j;
                float d = (xn + sWn[col]) - xs2 * sWs[col] * (float)acc[i][j];
                if (d <= thr) {
                    int pos = atomicAdd(&sCnt[row], 1);
                    if (pos < CAND_CAP)
                        sCand[row * CAND_CAP + pos] = (unsigned short)(c0 + col);
                }
            }
        }
    }

    __syncthreads();
    if (tid < 128) {
        int r = r0 + tid;
        int cnt = sCnt[tid];
        g_ccount[r] = cnt;
        int m = cnt < CAND_CAP ? cnt : CAND_CAP;
        for (int i = 0; i < m; i++)
            g_cand[(size_t)r * CAND_CAP + i] = sCand[tid * CAND_CAP + i];
    }
}

// ============================================================
// pass 2: exact fp32 verify of candidates; first-index tie-break
// ============================================================
__global__ void __launch_bounds__(256)
vq_pass2(const float* __restrict__ X, const float* __restrict__ W) {
    const int w = threadIdx.x >> 5, lane = threadIdx.x & 31;
    const int r = blockIdx.x * 8 + w;
    const float* xr = X + (size_t)r * DIM;
    float xv[16];
#pragma unroll
    for (int i = 0; i < 16; i++) xv[i] = xr[lane + 32 * i];
    const float xn = g_xnorm[r];
    const int cnt = g_ccount[r];
    unsigned long long best = 0xFFFFFFFFFFFFFFFFull;

    if (cnt <= CAND_CAP) {
        for (int c = 0; c < cnt; c++) {
            int idx = g_cand[(size_t)r * CAND_CAP + c];
            const float* wr = W + (size_t)idx * DIM;
            float s = 0.f;
#pragma unroll
            for (int i = 0; i < 16; i++) s += xv[i] * wr[lane + 32 * i];
#pragma unroll
            for (int o = 16; o > 0; o >>= 1) s += __shfl_xor_sync(0xffffffffu, s, o);
            float d = (xn + g_wnorm[idx]) - 2.0f * s;
            unsigned long long p =
                ((unsigned long long)__float_as_uint(d) << 32) | (unsigned)idx;
            if (p < best) best = p;
        }
    } else {                                  // overflow: exact scan of all codes
        for (int idx = 0; idx < KCODES; idx++) {
            const float* wr = W + (size_t)idx * DIM;
            float s = 0.f;
#pragma unroll
            for (int i = 0; i < 16; i++) s += xv[i] * wr[lane + 32 * i];
#pragma unroll
            for (int o = 16; o > 0; o >>= 1) s += __shfl_xor_sync(0xffffffffu, s, o);
            float d = (xn + g_wnorm[idx]) - 2.0f * s;
            unsigned long long p =
                ((unsigned long long)__float_as_uint(d) << 32) | (unsigned)idx;
            if (p < best) best = p;
        }
    }
    if (lane == 0) {
        int idx = (int)(best & 0xFFFFFFFFu);
        g_idx[r] = idx;
        atomicAdd(&g_counts[idx], 1);
    }
}

// ============================================================
// output: quantized_st + encodings + SSE
// outq is out+1 (4B-aligned) -> scalar stores; oute 8B-aligned -> float2.
// ============================================================
__global__ void __launch_bounds__(256)
vq_output_kernel(const float* __restrict__ X, const float* __restrict__ W,
                 float* __restrict__ outq, float* __restrict__ oute) {
    const int tid = threadIdx.x;
    const int r0  = blockIdx.x * 64;
    const int sub = tid >> 7, c4 = tid & 127;
    double lsum = 0.0;
#pragma unroll 4
    for (int i = 0; i < 32; i++) {
        int r = r0 + i * 2 + sub;
        int idx = g_idx[r];
        float4 xv = ((const float4*)(X + (size_t)r * DIM))[c4];
        float4 qv = ((const float4*)(W + (size_t)idx * DIM))[c4];
        float dx = qv.x - xv.x, dy = qv.y - xv.y, dz = qv.z - xv.z, dw = qv.w - xv.w;
        float* op = outq + (size_t)r * DIM + c4 * 4;
        op[0] = xv.x + dx; op[1] = xv.y + dy;
        op[2] = xv.z + dz; op[3] = xv.w + dw;
        lsum += (double)dx * dx + (double)dy * dy + (double)dz * dz + (double)dw * dw;
    }
    float2 z2 = make_float2(0.f, 0.f);
    for (int f = tid; f < 64 * (KCODES / 2); f += 256) {
        int row = f >> 9, q = f & 511;
        ((float2*)(oute + (size_t)(r0 + row) * KCODES))[q] = z2;
    }
    __syncthreads();
    if (tid < 64) {
        int r = r0 + tid;
        oute[(size_t)r * KCODES + g_idx[r]] = 1.0f;
    }
#pragma unroll
    for (int o = 16; o > 0; o >>= 1) lsum += __shfl_down_sync(0xffffffffu, lsum, o);
    __shared__ double sd[8];
    if ((tid & 31) == 0) sd[tid >> 5] = lsum;
    __syncthreads();
    if (tid == 0) {
        double t = 0.0;
        for (int v = 0; v < 8; v++) t += sd[v];
        atomicAdd(&g_sse, t);
    }
}

// ============================================================
__global__ void vq_finalize_kernel(float* __restrict__ out) {
    __shared__ float red[32];
    int tid = threadIdx.x;
    float p = (float)g_counts[tid] / 65536.0f;
    float t = p * logf(p + 1e-10f);
#pragma unroll
    for (int o = 16; o > 0; o >>= 1) t += __shfl_down_sync(0xffffffffu, t, o);
    if ((tid & 31) == 0) red[tid >> 5] = t;
    __syncthreads();
    if (tid < 32) {
        float v = red[tid];
#pragma unroll
        for (int o = 16; o > 0; o >>= 1) v += __shfl_down_sync(0xffffffffu, v, o);
        if (tid == 0) {
            out[PERP_OFF] = expf(-v);
            float m = (float)(g_sse / 33554432.0);
            out[0] = m + 0.25f * m;
        }
    }
}

// ============================================================
extern "C" void kernel_launch(void* const* d_in, const int* in_sizes, int n_in,
                              void* d_out, int out_size) {
    const float* X = (const float*)d_in[0];
    const float* W = (const float*)d_in[1];
    if (n_in >= 2 && in_sizes[0] == KCODES * DIM && in_sizes[1] == N_ROWS * DIM) {
        const float* t = X; X = W; W = t;
    }
    float* out  = (float*)d_out;
    float* outq = out + QUANT_OFF;
    float* oute = out + ENC_OFF;

    cudaFuncSetAttribute(vq_pass1,
                         cudaFuncAttributeMaxDynamicSharedMemorySize, SMTOT);

    vq_wprep<<<128, 256>>>(W);
    vq_xprep<<<N_ROWS / 32, 256>>>(X);
    vq_pass1<<<N_ROWS / 128, 256, SMTOT>>>();
    vq_pass2<<<N_ROWS / 8, 256>>>(X, W);
    vq_output_kernel<<<1024, 256>>>(X, W, outq, oute);
    vq_finalize_kernel<<<1, 1024>>>(out);
}

// round 8
// speedup vs baseline: 4.8098x; 4.8098x over previous
#include <cuda_runtime.h>
#include <cstdint>
#include <math.h>

#define N_ROWS 65536
#define DIM    512
#define KCODES 1024

#define QUANT_OFF 1
#define PERP_OFF  (1 + N_ROWS * DIM)
#define ENC_OFF   (2 + (size_t)N_ROWS * DIM)

// main kernel tiling: CTA = 64 rows x 1024 codes (8 chunks of 128)
#define BM 64
#define BN 128
#define KC 64                 // k per B staging chunk
#define ASTRIDE 516           // floats per A smem row

// smem byte offsets
#define SM_A    0             // [64][516] f32 = 132096
#define SM_B    132096        // 2 x [128][64] f32 (xor-swizzled cols) = 65536
#define SM_BBUF 32768
#define SM_WN   197632        // 128 f32
#define SM_XN   198144        // 64 f32
#define SM_PART 198400        // 64x4 f32
#define SM_BEST 199424        // 64 u64
#define SM_TOT  199936

// ---- scratch ----
__device__ float  g_wnorm[KCODES];
__device__ int    g_idx[N_ROWS];
__device__ int    g_counts[KCODES];
__device__ double g_sse;

// ---- helpers ----
static __device__ __forceinline__ uint64_t cvta_g(const void* p) {
    uint64_t a; asm("cvta.to.global.u64 %0, %1;" : "=l"(a) : "l"(p)); return a;
}
static __device__ __forceinline__ uint32_t smem_u32(const void* p) {
    uint32_t a;
    asm("{ .reg .u64 t; cvta.to.shared.u64 t, %1; cvt.u32.u64 %0, t; }" : "=r"(a) : "l"(p));
    return a;
}
static __device__ __forceinline__ void cp16(uint32_t s, uint64_t g) {
    asm volatile("cp.async.cg.shared.global [%0], [%1], 16;" :: "r"(s), "l"(g));
}
#define CP_COMMIT() asm volatile("cp.async.commit_group;")
#define CP_WAIT(n)  asm volatile("cp.async.wait_group %0;" :: "n"(n))

// packed fp32x2 FMA: lanes accumulate independent (even-k, odd-k) partial dots
static __device__ __forceinline__ void fma2(unsigned long long& c,
                                            unsigned long long a,
                                            unsigned long long b) {
    asm("fma.rn.f32x2 %0, %1, %2, %0;" : "+l"(c) : "l"(a), "l"(b));
}
static __device__ __forceinline__ float unpack_sum(unsigned long long v) {
    float lo, hi;
    asm("mov.b64 {%0,%1}, %2;" : "=f"(lo), "=f"(hi) : "l"(v));
    return lo + hi;
}

// ============================================================
// prep: wnorm per code + zero counts/sse
// ============================================================
__global__ void vq_prep_kernel(const float* __restrict__ W) {
    int w = threadIdx.x >> 5, lane = threadIdx.x & 31;
    int code = blockIdx.x * 8 + w;
    const float* row = W + (size_t)code * DIM;
    float s = 0.f;
#pragma unroll
    for (int t = 0; t < DIM / 32; t++) { float v = row[lane + t * 32]; s += v * v; }
#pragma unroll
    for (int o = 16; o > 0; o >>= 1) s += __shfl_down_sync(0xffffffffu, s, o);
    if (lane == 0) g_wnorm[code] = s;
    if (blockIdx.x == 0) {
        for (int i = threadIdx.x; i < KCODES; i += blockDim.x) g_counts[i] = 0;
        if (threadIdx.x == 0) g_sse = 0.0;
    }
}

// ============================================================
// B chunk staging: [128 codes][64 k] f32, 16B-col xor swizzle
// ============================================================
static __device__ __forceinline__ void stage_b(
    uint32_t sb, const float* __restrict__ W, int c0, int kc, int buf, int tid)
{
    uint64_t wsrc = cvta_g(W) + (size_t)c0 * (DIM * 4) + kc * (KC * 4);
    uint32_t dst = sb + SM_B + buf * SM_BBUF;
#pragma unroll
    for (int i = 0; i < 8; i++) {
        int f = tid + i * 256;          // 0..2047
        int code = f >> 4, k4 = f & 15;
        int col = k4 ^ (code & 15);
        cp16(dst + code * 256 + col * 16,
             wsrc + (size_t)code * (DIM * 4) + k4 * 16);
    }
}

// ============================================================
// main: f32x2 exact GEMM + fused argmin
// 256 thr = 16(tr) x 16(tc); thread = 4 rows x 8 codes (codes j*16+tc)
// ============================================================
__global__ void __launch_bounds__(256, 1)
vq_main(const float* __restrict__ X, const float* __restrict__ W) {
    extern __shared__ __align__(16) char smem[];
    const uint32_t sb = smem_u32(smem);
    float* As = (float*)smem;
    float* sWn = (float*)(smem + SM_WN);
    float* sXn = (float*)(smem + SM_XN);
    float* sPart = (float*)(smem + SM_PART);
    unsigned long long* sBest = (unsigned long long*)(smem + SM_BEST);

    const int tid = threadIdx.x;
    const int tr = tid >> 4, tc = tid & 15;
    const int r0 = blockIdx.x * BM;

    // stage A (64 x 512 f32 -> stride-516 rows) + B chunk 0, one group
    {
        uint64_t xsrc = cvta_g(X) + (size_t)r0 * (DIM * 4);
#pragma unroll
        for (int i = 0; i < 32; i++) {
            int f = tid + i * 256;          // 0..8191 16B chunks
            int row = f >> 7, c4 = f & 127;
            cp16(sb + SM_A + row * (ASTRIDE * 4) + c4 * 16,
                 xsrc + (size_t)row * (DIM * 4) + c4 * 16);
        }
    }
    stage_b(sb, W, 0, 0, 0, tid);
    CP_COMMIT();

    if (tid < BM) sBest[tid] = 0xFFFFFFFFFFFFFFFFull;

    int t = 0;
    for (int nc = 0; nc < 8; nc++) {
        const int c0 = nc * BN;
        unsigned long long acc[4][8];
#pragma unroll
        for (int i = 0; i < 4; i++)
#pragma unroll
            for (int j = 0; j < 8; j++) acc[i][j] = 0ull;

        for (int kc = 0; kc < 8; kc++, t++) {
            __syncthreads();             // all warps done reading buf^1 (t-1)
            if (t + 1 < 64) {
                int nt = t + 1;
                stage_b(sb, W, (nt >> 3) * BN, nt & 7, nt & 1, tid);
                CP_COMMIT();
                CP_WAIT(1);              // data for t landed
            } else {
                CP_WAIT(0);
            }
            __syncthreads();

            if (t == 0) {                // A ready: xnorm (one-time)
                int row = tid >> 2, part = tid & 3;
                const float* ap = As + row * ASTRIDE + part * 128;
                float s = 0.f;
#pragma unroll 8
                for (int q = 0; q < 128; q++) { float v = ap[q]; s += v * v; }
                sPart[row * 4 + part] = s;
                __syncthreads();
                if (tid < BM) {
                    float* p = sPart + tid * 4;
                    sXn[tid] = (p[0] + p[1]) + (p[2] + p[3]);
                }
            }
            if (kc == 0 && tid < BN) sWn[tid] = g_wnorm[c0 + tid];

            const char* pB = smem + SM_B + (t & 1) * SM_BBUF + tc * 256;
            const float* pA = As + (tr * 4) * ASTRIDE + kc * KC;
#pragma unroll
            for (int k4 = 0; k4 < 16; k4++) {
                const int col16 = (k4 ^ tc) << 4;
                ulonglong2 bv[8];
#pragma unroll
                for (int j = 0; j < 8; j++)
                    bv[j] = *(const ulonglong2*)(pB + j * 4096 + col16);
#pragma unroll
                for (int i = 0; i < 4; i++) {
                    ulonglong2 av =
                        *(const ulonglong2*)(pA + i * ASTRIDE + k4 * 4);
#pragma unroll
                    for (int j = 0; j < 8; j++) {
                        fma2(acc[i][j], av.x, bv[j].x);
                        fma2(acc[i][j], av.y, bv[j].y);
                    }
                }
            }
        }

        // ---- epilogue: distances + per-row argmin (first-index ties) ----
#pragma unroll
        for (int i = 0; i < 4; i++) {
            int row = tr * 4 + i;
            float xn = sXn[row];
            unsigned long long best = 0xFFFFFFFFFFFFFFFFull;
#pragma unroll
            for (int j = 0; j < 8; j++) {
                int col = j * 16 + tc;
                float dot = unpack_sum(acc[i][j]);
                float d = (xn + sWn[col]) - 2.0f * dot;   // reference fp32 formula
                unsigned key = __float_as_uint(d);
                key = (key & 0x80000000u) ? ~key : (key | 0x80000000u);
                unsigned long long pk =
                    ((unsigned long long)key << 32) | (unsigned)(c0 + col);
                if (pk < best) best = pk;
            }
            atomicMin(&sBest[row], best);
        }
    }

    __syncthreads();
    if (tid < BM) {
        int idx = (int)(sBest[tid] & 0xFFFFFFFFu);
        g_idx[r0 + tid] = idx;
        atomicAdd(&g_counts[idx], 1);
    }
}

// ============================================================
// output: quantized_st + encodings + SSE
// outq is out+1 (4B-aligned) -> scalar stores; oute 8B-aligned -> float2.
// ============================================================
__global__ void __launch_bounds__(256)
vq_output_kernel(const float* __restrict__ X, const float* __restrict__ W,
                 float* __restrict__ outq, float* __restrict__ oute) {
    const int tid = threadIdx.x;
    const int r0  = blockIdx.x * 64;
    const int sub = tid >> 7, c4 = tid & 127;
    double lsum = 0.0;
#pragma unroll 4
    for (int i = 0; i < 32; i++) {
        int r = r0 + i * 2 + sub;
        int idx = g_idx[r];
        float4 xv = ((const float4*)(X + (size_t)r * DIM))[c4];
        float4 qv = ((const float4*)(W + (size_t)idx * DIM))[c4];
        float dx = qv.x - xv.x, dy = qv.y - xv.y, dz = qv.z - xv.z, dw = qv.w - xv.w;
        float* op = outq + (size_t)r * DIM + c4 * 4;
        op[0] = xv.x + dx; op[1] = xv.y + dy;
        op[2] = xv.z + dz; op[3] = xv.w + dw;
        lsum += (double)dx * dx + (double)dy * dy + (double)dz * dz + (double)dw * dw;
    }
    float2 z2 = make_float2(0.f, 0.f);
    for (int f = tid; f < 64 * (KCODES / 2); f += 256) {
        int row = f >> 9, q = f & 511;
        ((float2*)(oute + (size_t)(r0 + row) * KCODES))[q] = z2;
    }
    __syncthreads();
    if (tid < 64) {
        int r = r0 + tid;
        oute[(size_t)r * KCODES + g_idx[r]] = 1.0f;
    }
#pragma unroll
    for (int o = 16; o > 0; o >>= 1) lsum += __shfl_down_sync(0xffffffffu, lsum, o);
    __shared__ double sd[8];
    if ((tid & 31) == 0) sd[tid >> 5] = lsum;
    __syncthreads();
    if (tid == 0) {
        double s = 0.0;
        for (int v = 0; v < 8; v++) s += sd[v];
        atomicAdd(&g_sse, s);
    }
}

// ============================================================
__global__ void vq_finalize_kernel(float* __restrict__ out) {
    __shared__ float red[32];
    int tid = threadIdx.x;
    float p = (float)g_counts[tid] / 65536.0f;
    float t = p * logf(p + 1e-10f);
#pragma unroll
    for (int o = 16; o > 0; o >>= 1) t += __shfl_down_sync(0xffffffffu, t, o);
    if ((tid & 31) == 0) red[tid >> 5] = t;
    __syncthreads();
    if (tid < 32) {
        float v = red[tid];
#pragma unroll
        for (int o = 16; o > 0; o >>= 1) v += __shfl_down_sync(0xffffffffu, v, o);
        if (tid == 0) {
            out[PERP_OFF] = expf(-v);
            float m = (float)(g_sse / 33554432.0);
            out[0] = m + 0.25f * m;
        }
    }
}

// ============================================================
extern "C" void kernel_launch(void* const* d_in, const int* in_sizes, int n_in,
                              void* d_out, int out_size) {
    const float* X = (const float*)d_in[0];
    const float* W = (const float*)d_in[1];
    if (n_in >= 2 && in_sizes[0] == KCODES * DIM && in_sizes[1] == N_ROWS * DIM) {
        const float* t = X; X = W; W = t;
    }
    float* out  = (float*)d_out;
    float* outq = out + QUANT_OFF;
    float* oute = out + ENC_OFF;

    cudaFuncSetAttribute(vq_main,
                         cudaFuncAttributeMaxDynamicSharedMemorySize, SM_TOT);

    vq_prep_kernel<<<128, 256>>>(W);
    vq_main<<<N_ROWS / BM, 256, SM_TOT>>>(X, W);
    vq_output_kernel<<<1024, 256>>>(X, W, outq, oute);
    vq_finalize_kernel<<<1, 1024>>>(out);
}